// round 3
// baseline (speedup 1.0000x reference)
#include <cuda_runtime.h>
#include <math.h>

// Problem constants
#define Bsz   512
#define Hsz   512
#define TT    120
#define Fsz   72
#define INsz  713
#define CONDsz 640
#define OUT_ROW (TT*Fsz)   // 8640, row stride of d_out per batch element

// ---------------- scratch (device globals; no runtime alloc allowed) ----------------
__device__ float g_enc_in[Bsz*TT*Hsz];     // [B][T][H] encoder embedded input
__device__ float g_cond[Bsz*CONDsz];       // [B][640]  label (x) class_embedding
__device__ float g_x[Bsz*Hsz];             // decoder embedding output (LSTM input)
__device__ float g_h[2][2][Bsz*Hsz];       // [layer][pingpong][B*H]
__device__ float g_c[2][Bsz*Hsz];          // [layer][B*H]

__device__ __forceinline__ float sigf(float x) { return 1.0f / (1.0f + expf(-x)); }

// ---- packed fp32x2 helpers (Blackwell FFMA2; only reachable via PTX) ----
__device__ __forceinline__ unsigned long long pack2(float a) {
    unsigned long long d;
    asm("mov.b64 %0, {%1, %1};" : "=l"(d) : "f"(a));
    return d;
}
__device__ __forceinline__ void fma2(unsigned long long& d,
                                     unsigned long long a,
                                     unsigned long long b) {
    asm("fma.rn.f32x2 %0, %1, %2, %0;" : "+l"(d) : "l"(a), "l"(b));
}
__device__ __forceinline__ float2 unpack2(unsigned long long v) {
    float2 r;
    asm("mov.b64 {%0, %1}, %2;" : "=f"(r.x), "=f"(r.y) : "l"(v));
    return r;
}

// ---------------- init: zero h and c ----------------
__global__ void zero_state_kernel() {
    int i = blockIdx.x * blockDim.x + threadIdx.x;
    if (i < Bsz*Hsz) {
        g_h[0][0][i] = 0.f; g_h[0][1][i] = 0.f;
        g_h[1][0][i] = 0.f; g_h[1][1][i] = 0.f;
        g_c[0][i] = 0.f;    g_c[1][i] = 0.f;
    }
}

// ---------------- encoder input embedding: prelu(traj @ W^T + b) ----------------
__global__ void enc_in_kernel(const float* __restrict__ traj,
                              const float* __restrict__ W,
                              const float* __restrict__ bias,
                              const float* __restrict__ prelu_a) {
    int idx = blockIdx.x * blockDim.x + threadIdx.x;
    if (idx >= Bsz*TT*Hsz) return;
    int h  = idx & (Hsz - 1);
    int bt = idx >> 9;
    float x0 = traj[bt*3+0], x1 = traj[bt*3+1], x2 = traj[bt*3+2];
    float v = bias[h] + W[h*3+0]*x0 + W[h*3+1]*x1 + W[h*3+2]*x2;
    float a = prelu_a[0];
    g_enc_in[idx] = (v >= 0.f) ? v : a * v;
}

// ---------------- condition feature: cond[b, i*64+j] = label[b,i]*ce[b,j] ----------------
__global__ void cond_kernel(const float* __restrict__ label,
                            const float* __restrict__ ce) {
    int idx = blockIdx.x * blockDim.x + threadIdx.x;
    if (idx >= Bsz*CONDsz) return;
    int b = idx / CONDsz;
    int r = idx - b*CONDsz;
    int i = r >> 6;        // /64
    int j = r & 63;
    g_cond[idx] = label[b*10 + i] * ce[b*64 + j];
}

// ---------------- fused LSTM step (FFMA2 packed inner loop) ----------------
// gates = x@Wih^T + bih + h@Whh^T + bhh ; cell update fused.
// CTA: 64 batch rows x 32 hidden units (x4 gates -> 128 weight rows). 256 threads.
// smem gate-interleaved: ws[k][n'] with n' = jj*4+gate. Thread micro-tile:
// 4 batch x 8 n' (= 2 hidden units x 4 gates). Accumulators are packed f32x2
// pairs along n' so the mainloop runs on the double-rate FFMA2 path.
__global__ __launch_bounds__(256) void lstm_step_kernel(
    const float* __restrict__ x, int x_stride,
    const float* __restrict__ h_in,
    const float* __restrict__ Wih, const float* __restrict__ Whh,
    const float* __restrict__ bih, const float* __restrict__ bhh,
    float* __restrict__ h_out, float* __restrict__ c)
{
    const int m0 = blockIdx.x * 64;
    const int j0 = blockIdx.y * 32;
    __shared__ __align__(16) float xs[16][64];    // [k][m]
    __shared__ __align__(16) float ws[16][128];   // [k][n'], n' = jj*4+g

    unsigned long long acc2[4][4];   // [mi][pair], pair p covers n' = 2p, 2p+1
#pragma unroll
    for (int i = 0; i < 4; i++)
#pragma unroll
        for (int j = 0; j < 4; j++) acc2[i][j] = 0ULL;

    const int tid = threadIdx.x;
    const int tx = tid & 15, ty = tid >> 4;
    // loader roles
    const int xm = tid >> 2, xq = tid & 3;   // xs: row m (0..63), quarter of 16 k's
    const int wn = tid >> 1, wh = tid & 1;   // ws: n' (0..127), half of 16 k's
    const int wjj = wn >> 2, wg = wn & 3;
    const int wrow = wg * Hsz + j0 + wjj;    // weight row index (gate-major)

#pragma unroll
    for (int phase = 0; phase < 2; phase++) {
        const float* A = phase ? h_in : x;
        const int as = phase ? Hsz : x_stride;
        const float* W = phase ? Whh : Wih;
        const float* Aptr = A + (size_t)(m0 + xm) * as;
        const float* Wptr = W + (size_t)wrow * Hsz;
        for (int k0 = 0; k0 < Hsz; k0 += 16) {
            // prefetch globals into registers (overlaps with previous tile's math)
            float4 av = *(const float4*)(Aptr + k0 + xq * 4);
            float4 w0 = *(const float4*)(Wptr + k0 + wh * 8);
            float4 w1 = *(const float4*)(Wptr + k0 + wh * 8 + 4);
            __syncthreads();   // previous tile fully consumed
            xs[xq*4+0][xm] = av.x; xs[xq*4+1][xm] = av.y;
            xs[xq*4+2][xm] = av.z; xs[xq*4+3][xm] = av.w;
            ws[wh*8+0][wn] = w0.x; ws[wh*8+1][wn] = w0.y;
            ws[wh*8+2][wn] = w0.z; ws[wh*8+3][wn] = w0.w;
            ws[wh*8+4][wn] = w1.x; ws[wh*8+5][wn] = w1.y;
            ws[wh*8+6][wn] = w1.z; ws[wh*8+7][wn] = w1.w;
            __syncthreads();
#pragma unroll
            for (int kk = 0; kk < 16; kk++) {
                float4 a4 = *(const float4*)&xs[kk][ty * 4];
                ulonglong2 b01 = *(const ulonglong2*)&ws[kk][tx * 8];
                ulonglong2 b23 = *(const ulonglong2*)&ws[kk][tx * 8 + 4];
                unsigned long long bn[4] = {b01.x, b01.y, b23.x, b23.y};
                unsigned long long am[4] = {pack2(a4.x), pack2(a4.y),
                                            pack2(a4.z), pack2(a4.w)};
#pragma unroll
                for (int mi = 0; mi < 4; mi++)
#pragma unroll
                    for (int ni = 0; ni < 4; ni++)
                        fma2(acc2[mi][ni], am[mi], bn[ni]);
            }
        }
    }

    // epilogue: bias + cell update (gate order i,f,g,o)
#pragma unroll
    for (int jl = 0; jl < 2; jl++) {
        int j = j0 + tx * 2 + jl;
        float bi = bih[j]         + bhh[j];
        float bf = bih[Hsz + j]   + bhh[Hsz + j];
        float bg = bih[2*Hsz + j] + bhh[2*Hsz + j];
        float bo = bih[3*Hsz + j] + bhh[3*Hsz + j];
#pragma unroll
        for (int mi = 0; mi < 4; mi++) {
            int m = m0 + ty * 4 + mi;
            float2 p_if = unpack2(acc2[mi][jl*2 + 0]);   // gates i, f
            float2 p_go = unpack2(acc2[mi][jl*2 + 1]);   // gates g, o
            float gi = p_if.x + bi;
            float gf = p_if.y + bf;
            float gg = p_go.x + bg;
            float go = p_go.y + bo;
            float cold = c[m * Hsz + j];
            float cn = sigf(gf) * cold + sigf(gi) * tanhf(gg);
            c[m * Hsz + j] = cn;
            h_out[m * Hsz + j] = sigf(go) * tanhf(cn);
        }
    }
}

// ---------------- decoder embedding step ----------------
// x = prelu([prev_out | cond] @ emb_W[:, :712]^T + (emb_b + emb_W[:,712]*ts))
// prev = d_out + (t-1)*72 (row stride 8640), nullptr at t=0.
__global__ __launch_bounds__(256) void emb_step_kernel(
    const float* __restrict__ prev,
    const float* __restrict__ emb_W, const float* __restrict__ emb_b,
    float ts, const float* __restrict__ prelu_a)
{
    const int m0 = blockIdx.x * 32;
    const int n0 = blockIdx.y * 64;
    __shared__ __align__(16) float xs[16][32];   // [k][m]
    __shared__ __align__(16) float ws[16][64];   // [k][n]

    float acc[2][4];
#pragma unroll
    for (int i = 0; i < 2; i++)
#pragma unroll
        for (int j = 0; j < 4; j++) acc[i][j] = 0.f;

    const int tid = threadIdx.x;
    const int tx = tid & 15, ty = tid >> 4;

    for (int k0 = 0; k0 < 712; k0 += 16) {
        // stage loads in registers
        float xv[2], wv[4];
#pragma unroll
        for (int it = 0; it < 2; it++) {
            int i = tid + it * 256;           // < 512
            int mm = i >> 4, kk = i & 15;
            int k = k0 + kk;
            int b = m0 + mm;
            float v = 0.f;
            if (k < 72)       { if (prev) v = prev[(size_t)b * OUT_ROW + k]; }
            else if (k < 712) { v = g_cond[b * CONDsz + (k - 72)]; }
            xv[it] = v;
        }
#pragma unroll
        for (int it = 0; it < 4; it++) {
            int i = tid + it * 256;           // < 1024
            int nn = i >> 4, kk = i & 15;
            int k = k0 + kk;
            wv[it] = (k < 712) ? emb_W[(size_t)(n0 + nn) * INsz + k] : 0.f;
        }
        __syncthreads();
#pragma unroll
        for (int it = 0; it < 2; it++) {
            int i = tid + it * 256;
            xs[i & 15][i >> 4] = xv[it];
        }
#pragma unroll
        for (int it = 0; it < 4; it++) {
            int i = tid + it * 256;
            ws[i & 15][i >> 4] = wv[it];
        }
        __syncthreads();
#pragma unroll
        for (int kk = 0; kk < 16; kk++) {
            float2 a2 = *(const float2*)&xs[kk][ty * 2];
            float4 b4 = *(const float4*)&ws[kk][tx * 4];
            float am[2] = {a2.x, a2.y};
            float bn[4] = {b4.x, b4.y, b4.z, b4.w};
#pragma unroll
            for (int mi = 0; mi < 2; mi++)
#pragma unroll
                for (int ni = 0; ni < 4; ni++)
                    acc[mi][ni] = fmaf(am[mi], bn[ni], acc[mi][ni]);
        }
    }

    float a = prelu_a[0];
#pragma unroll
    for (int mi = 0; mi < 2; mi++) {
        int m = m0 + ty * 2 + mi;
#pragma unroll
        for (int ni = 0; ni < 4; ni++) {
            int n = n0 + tx * 4 + ni;
            float v = acc[mi][ni] + emb_b[n] + emb_W[(size_t)n * INsz + 712] * ts;
            g_x[m * Hsz + n] = (v >= 0.f) ? v : a * v;
        }
    }
}

// ---------------- output projection: out = h @ out_W^T + out_b ----------------
__global__ void out_step_kernel(const float* __restrict__ h,
                                const float* __restrict__ out_W,
                                const float* __restrict__ out_b,
                                float* __restrict__ outp)  // d_out + t*72
{
    __shared__ float hs[8][512];
    __shared__ float ws[64][72];
    const int tid = threadIdx.y * 72 + threadIdx.x;   // 0..575
    const int m0 = blockIdx.x * 8;
    for (int i = tid; i < 8 * 512; i += 576)
        hs[i >> 9][i & 511] = h[(size_t)(m0 + (i >> 9)) * Hsz + (i & 511)];

    float acc = 0.f;
    const int n = threadIdx.x, my = threadIdx.y;
    for (int k0 = 0; k0 < 512; k0 += 64) {
        __syncthreads();
        for (int i = tid; i < 72 * 64; i += 576) {
            int nn = i >> 6, kk = i & 63;
            ws[kk][nn] = out_W[(size_t)nn * Hsz + k0 + kk];
        }
        __syncthreads();
#pragma unroll
        for (int kk = 0; kk < 64; kk++)
            acc = fmaf(hs[my][k0 + kk], ws[kk][n], acc);
    }
    outp[(size_t)(m0 + my) * OUT_ROW + n] = acc + out_b[n];
}

// ---------------- host orchestration ----------------
extern "C" void kernel_launch(void* const* d_in, const int* in_sizes, int n_in,
                              void* d_out, int out_size) {
    const float* label     = (const float*)d_in[1];
    const float* ce        = (const float*)d_in[2];
    const float* traj      = (const float*)d_in[3];
    const float* enc_emb_W = (const float*)d_in[4];
    const float* enc_emb_b = (const float*)d_in[5];
    const float* prelu_a   = (const float*)d_in[6];
    const float* emb_W     = (const float*)d_in[7];
    const float* emb_b     = (const float*)d_in[8];
    const float* out_W     = (const float*)d_in[9];
    const float* out_b     = (const float*)d_in[10];
    const float* enc_Wih   = (const float*)d_in[11];
    const float* enc_Whh   = (const float*)d_in[12];
    const float* enc_bih   = (const float*)d_in[13];
    const float* enc_bhh   = (const float*)d_in[14];
    const float* dec_Wih   = (const float*)d_in[15];
    const float* dec_Whh   = (const float*)d_in[16];
    const float* dec_bih   = (const float*)d_in[17];
    const float* dec_bhh   = (const float*)d_in[18];
    float* out = (float*)d_out;

    // resolve device-global scratch addresses
    float *enc_in_p, *h_base, *c_base, *x_p;
    cudaGetSymbolAddress((void**)&enc_in_p, g_enc_in);
    cudaGetSymbolAddress((void**)&h_base,   g_h);
    cudaGetSymbolAddress((void**)&c_base,   g_c);
    cudaGetSymbolAddress((void**)&x_p,      g_x);
    const size_t HB = (size_t)Bsz * Hsz;
    float* hbuf[2][2] = {{h_base, h_base + HB}, {h_base + 2*HB, h_base + 3*HB}};
    float* cbuf[2]    = {c_base, c_base + HB};

    const int WLH = 4 * Hsz * Hsz;   // per-layer Wih/Whh element count
    const int BLH = 4 * Hsz;         // per-layer bias element count

    // init
    zero_state_kernel<<<(Bsz*Hsz + 255) / 256, 256>>>();
    enc_in_kernel<<<(Bsz*TT*Hsz + 255) / 256, 256>>>(traj, enc_emb_W, enc_emb_b, prelu_a);
    cond_kernel<<<(Bsz*CONDsz + 255) / 256, 256>>>(label, ce);

    dim3 lstm_grid(8, 16);
    dim3 emb_grid(16, 8);
    dim3 out_block(72, 8);

    int cur0 = 0, cur1 = 0;

    // ---- encoder ----
    for (int t = 0; t < TT; t++) {
        lstm_step_kernel<<<lstm_grid, 256>>>(
            enc_in_p + (size_t)t * Hsz, TT * Hsz,
            hbuf[0][cur0],
            enc_Wih, enc_Whh, enc_bih, enc_bhh,
            hbuf[0][cur0 ^ 1], cbuf[0]);
        cur0 ^= 1;
        lstm_step_kernel<<<lstm_grid, 256>>>(
            hbuf[0][cur0], Hsz,
            hbuf[1][cur1],
            enc_Wih + WLH, enc_Whh + WLH, enc_bih + BLH, enc_bhh + BLH,
            hbuf[1][cur1 ^ 1], cbuf[1]);
        cur1 ^= 1;
    }

    // ---- decoder (autoregressive, tf_rate = 0) ----
    for (int t = 0; t < TT; t++) {
        const float* prev = (t == 0) ? nullptr : (out + (size_t)(t - 1) * Fsz);
        float ts = (float)(t + 1) / (float)TT;
        emb_step_kernel<<<emb_grid, 256>>>(prev, emb_W, emb_b, ts, prelu_a);
        lstm_step_kernel<<<lstm_grid, 256>>>(
            x_p, Hsz,
            hbuf[0][cur0],
            dec_Wih, dec_Whh, dec_bih, dec_bhh,
            hbuf[0][cur0 ^ 1], cbuf[0]);
        cur0 ^= 1;
        lstm_step_kernel<<<lstm_grid, 256>>>(
            hbuf[0][cur0], Hsz,
            hbuf[1][cur1],
            dec_Wih + WLH, dec_Whh + WLH, dec_bih + BLH, dec_bhh + BLH,
            hbuf[1][cur1 ^ 1], cbuf[1]);
        cur1 ^= 1;
        out_step_kernel<<<64, out_block>>>(hbuf[1][cur1], out_W, out_b,
                                           out + (size_t)t * Fsz);
    }
}

// round 9
// speedup vs baseline: 1.1756x; 1.1756x over previous
#include <cuda_runtime.h>
#include <math.h>

// Problem constants
#define Bsz   512
#define Hsz   512
#define TT    120
#define Fsz   72
#define INsz  713
#define CONDsz 640
#define OUT_ROW (TT*Fsz)   // 8640, row stride of d_out per batch element

// ---------------- scratch (device globals; no runtime alloc allowed) ----------------
__device__ float g_enc_in[Bsz*TT*Hsz];     // [B][T][H] encoder embedded input
__device__ float g_cond[Bsz*CONDsz];       // [B][640]  label (x) class_embedding
__device__ float g_x[Bsz*Hsz];             // decoder embedding output (LSTM input)
__device__ float g_h[2][2][Bsz*Hsz];       // [layer][pingpong][B*H]
__device__ float g_c[2][Bsz*Hsz];          // [layer][B*H]

__device__ __forceinline__ float sigf(float x) { return 1.0f / (1.0f + expf(-x)); }

// ---- packed fp32x2 helpers (Blackwell FFMA2; only reachable via PTX) ----
__device__ __forceinline__ unsigned long long pack2(float a) {
    unsigned long long d;
    asm("mov.b64 %0, {%1, %1};" : "=l"(d) : "f"(a));
    return d;
}
__device__ __forceinline__ void fma2(unsigned long long& d,
                                     unsigned long long a,
                                     unsigned long long b) {
    asm("fma.rn.f32x2 %0, %1, %2, %0;" : "+l"(d) : "l"(a), "l"(b));
}
__device__ __forceinline__ float2 unpack2(unsigned long long v) {
    float2 r;
    asm("mov.b64 {%0, %1}, %2;" : "=f"(r.x), "=f"(r.y) : "l"(v));
    return r;
}

// ---------------- init: zero h and c ----------------
__global__ void zero_state_kernel() {
    int i = blockIdx.x * blockDim.x + threadIdx.x;
    if (i < Bsz*Hsz) {
        g_h[0][0][i] = 0.f; g_h[0][1][i] = 0.f;
        g_h[1][0][i] = 0.f; g_h[1][1][i] = 0.f;
        g_c[0][i] = 0.f;    g_c[1][i] = 0.f;
    }
}

// ---------------- encoder input embedding: prelu(traj @ W^T + b) ----------------
__global__ void enc_in_kernel(const float* __restrict__ traj,
                              const float* __restrict__ W,
                              const float* __restrict__ bias,
                              const float* __restrict__ prelu_a) {
    int idx = blockIdx.x * blockDim.x + threadIdx.x;
    if (idx >= Bsz*TT*Hsz) return;
    int h  = idx & (Hsz - 1);
    int bt = idx >> 9;
    float x0 = traj[bt*3+0], x1 = traj[bt*3+1], x2 = traj[bt*3+2];
    float v = bias[h] + W[h*3+0]*x0 + W[h*3+1]*x1 + W[h*3+2]*x2;
    float a = prelu_a[0];
    g_enc_in[idx] = (v >= 0.f) ? v : a * v;
}

// ---------------- condition feature: cond[b, i*64+j] = label[b,i]*ce[b,j] ----------------
__global__ void cond_kernel(const float* __restrict__ label,
                            const float* __restrict__ ce) {
    int idx = blockIdx.x * blockDim.x + threadIdx.x;
    if (idx >= Bsz*CONDsz) return;
    int b = idx / CONDsz;
    int r = idx - b*CONDsz;
    int i = r >> 6;        // /64
    int j = r & 63;
    g_cond[idx] = label[b*10 + i] * ce[b*64 + j];
}

// ---------------- fused LSTM step (FFMA2 + double-buffered smem) ----------------
// gates = x@Wih^T + bih + h@Whh^T + bhh ; cell update fused.
// CTA: 32 batch rows x 16 hidden units (x4 gates -> 64 weight rows). 128 threads.
// Grid (16, 32) = 512 CTAs -> ~3.5 CTAs / ~14 warps per SM.
// K space is flattened to 64 tiles of 16 (tiles 0..31 = x@Wih, 32..63 = h@Whh).
// Two-stage smem pipeline, ONE __syncthreads per tile:
//   iter i: LDG(tile i+1) -> compute buf[i&1] -> STS buf[(i+1)&1] -> bar
// The 16-k compute block (~190 issue slots) covers the LDG latency.
__global__ __launch_bounds__(128) void lstm_step_kernel(
    const float* __restrict__ x, int x_stride,
    const float* __restrict__ h_in,
    const float* __restrict__ Wih, const float* __restrict__ Whh,
    const float* __restrict__ bih, const float* __restrict__ bhh,
    float* __restrict__ h_out, float* __restrict__ c)
{
    const int m0 = blockIdx.x * 32;
    const int j0 = blockIdx.y * 16;
    __shared__ __align__(16) float xs[2][16][32];   // [stage][k][m]
    __shared__ __align__(16) float ws[2][16][64];   // [stage][k][n'], n' = jj*4+g

    unsigned long long acc2[4][2];   // [mi][pair]: pair0 = (i,f), pair1 = (g,o)
#pragma unroll
    for (int i = 0; i < 4; i++) { acc2[i][0] = 0ULL; acc2[i][1] = 0ULL; }

    const int tid = threadIdx.x;
    const int tx = tid & 15;         // hidden unit within tile (jj)
    const int ty = tid >> 4;         // m-group (0..7), 4 batch rows each
    // loader roles
    const int xm = tid >> 2, xq = tid & 3;   // xs: row m (0..31), quarter of 16 k's
    const int wn = tid >> 1, wh = tid & 1;   // ws: n' (0..63), half of 16 k's
    const int wjj = wn >> 2, wg = wn & 3;
    const int wrow = wg * Hsz + j0 + wjj;    // weight row index (gate-major)

    // per-phase base pointers for this thread's loader role
    const float* Aptr0 = x    + (size_t)(m0 + xm) * x_stride;
    const float* Aptr1 = h_in + (size_t)(m0 + xm) * Hsz;
    const float* Wptr0 = Wih + (size_t)wrow * Hsz;
    const float* Wptr1 = Whh + (size_t)wrow * Hsz;

    // ---- prologue: stage tile 0 into buffer 0 ----
    {
        float4 av = *(const float4*)(Aptr0 + xq * 4);
        float4 w0 = *(const float4*)(Wptr0 + wh * 8);
        float4 w1 = *(const float4*)(Wptr0 + wh * 8 + 4);
        xs[0][xq*4+0][xm] = av.x; xs[0][xq*4+1][xm] = av.y;
        xs[0][xq*4+2][xm] = av.z; xs[0][xq*4+3][xm] = av.w;
        ws[0][wh*8+0][wn] = w0.x; ws[0][wh*8+1][wn] = w0.y;
        ws[0][wh*8+2][wn] = w0.z; ws[0][wh*8+3][wn] = w0.w;
        ws[0][wh*8+4][wn] = w1.x; ws[0][wh*8+5][wn] = w1.y;
        ws[0][wh*8+6][wn] = w1.z; ws[0][wh*8+7][wn] = w1.w;
    }
    __syncthreads();

    // ---- main pipeline over 64 flattened K-tiles ----
    for (int i = 0; i < 64; i++) {
        float4 av, w0, w1;
        const bool have_next = (i + 1) < 64;
        if (have_next) {
            int nt = i + 1;
            int k0 = (nt & 31) * 16;
            const float* Ap = (nt < 32) ? Aptr0 : Aptr1;
            const float* Wp = (nt < 32) ? Wptr0 : Wptr1;
            av = *(const float4*)(Ap + k0 + xq * 4);
            w0 = *(const float4*)(Wp + k0 + wh * 8);
            w1 = *(const float4*)(Wp + k0 + wh * 8 + 4);
        }

        // compute on buffer i&1 (covers the prefetch LDG latency)
        const int cb = i & 1;
#pragma unroll
        for (int kk = 0; kk < 16; kk++) {
            float4 a4 = *(const float4*)&xs[cb][kk][ty * 4];        // 4 batch rows
            ulonglong2 b = *(const ulonglong2*)&ws[cb][kk][tx * 4]; // (i,f),(g,o)
            unsigned long long am[4] = {pack2(a4.x), pack2(a4.y),
                                        pack2(a4.z), pack2(a4.w)};
#pragma unroll
            for (int mi = 0; mi < 4; mi++) {
                fma2(acc2[mi][0], am[mi], b.x);
                fma2(acc2[mi][1], am[mi], b.y);
            }
        }

        if (have_next) {
            const int nb = (i + 1) & 1;
            xs[nb][xq*4+0][xm] = av.x; xs[nb][xq*4+1][xm] = av.y;
            xs[nb][xq*4+2][xm] = av.z; xs[nb][xq*4+3][xm] = av.w;
            ws[nb][wh*8+0][wn] = w0.x; ws[nb][wh*8+1][wn] = w0.y;
            ws[nb][wh*8+2][wn] = w0.z; ws[nb][wh*8+3][wn] = w0.w;
            ws[nb][wh*8+4][wn] = w1.x; ws[nb][wh*8+5][wn] = w1.y;
            ws[nb][wh*8+6][wn] = w1.z; ws[nb][wh*8+7][wn] = w1.w;
            __syncthreads();
        }
    }

    // epilogue: bias + cell update (gate order i,f,g,o); thread owns hidden j
    {
        int j = j0 + tx;
        float bi = bih[j]         + bhh[j];
        float bf = bih[Hsz + j]   + bhh[Hsz + j];
        float bg = bih[2*Hsz + j] + bhh[2*Hsz + j];
        float bo = bih[3*Hsz + j] + bhh[3*Hsz + j];
#pragma unroll
        for (int mi = 0; mi < 4; mi++) {
            int m = m0 + ty * 4 + mi;
            float2 p_if = unpack2(acc2[mi][0]);
            float2 p_go = unpack2(acc2[mi][1]);
            float gi = p_if.x + bi;
            float gf = p_if.y + bf;
            float gg = p_go.x + bg;
            float go = p_go.y + bo;
            float cold = c[m * Hsz + j];
            float cn = sigf(gf) * cold + sigf(gi) * tanhf(gg);
            c[m * Hsz + j] = cn;
            h_out[m * Hsz + j] = sigf(go) * tanhf(cn);
        }
    }
}

// ---------------- decoder embedding step ----------------
// x = prelu([prev_out | cond] @ emb_W[:, :712]^T + (emb_b + emb_W[:,712]*ts))
// prev = d_out + (t-1)*72 (row stride 8640), nullptr at t=0.
__global__ __launch_bounds__(256) void emb_step_kernel(
    const float* __restrict__ prev,
    const float* __restrict__ emb_W, const float* __restrict__ emb_b,
    float ts, const float* __restrict__ prelu_a)
{
    const int m0 = blockIdx.x * 32;
    const int n0 = blockIdx.y * 64;
    __shared__ __align__(16) float xs[16][32];   // [k][m]
    __shared__ __align__(16) float ws[16][64];   // [k][n]

    float acc[2][4];
#pragma unroll
    for (int i = 0; i < 2; i++)
#pragma unroll
        for (int j = 0; j < 4; j++) acc[i][j] = 0.f;

    const int tid = threadIdx.x;
    const int tx = tid & 15, ty = tid >> 4;

    for (int k0 = 0; k0 < 712; k0 += 16) {
        // stage loads in registers
        float xv[2], wv[4];
#pragma unroll
        for (int it = 0; it < 2; it++) {
            int i = tid + it * 256;           // < 512
            int mm = i >> 4, kk = i & 15;
            int k = k0 + kk;
            int b = m0 + mm;
            float v = 0.f;
            if (k < 72)       { if (prev) v = prev[(size_t)b * OUT_ROW + k]; }
            else if (k < 712) { v = g_cond[b * CONDsz + (k - 72)]; }
            xv[it] = v;
        }
#pragma unroll
        for (int it = 0; it < 4; it++) {
            int i = tid + it * 256;           // < 1024
            int nn = i >> 4, kk = i & 15;
            int k = k0 + kk;
            wv[it] = (k < 712) ? emb_W[(size_t)(n0 + nn) * INsz + k] : 0.f;
        }
        __syncthreads();
#pragma unroll
        for (int it = 0; it < 2; it++) {
            int i = tid + it * 256;
            xs[i & 15][i >> 4] = xv[it];
        }
#pragma unroll
        for (int it = 0; it < 4; it++) {
            int i = tid + it * 256;
            ws[i & 15][i >> 4] = wv[it];
        }
        __syncthreads();
#pragma unroll
        for (int kk = 0; kk < 16; kk++) {
            float2 a2 = *(const float2*)&xs[kk][ty * 2];
            float4 b4 = *(const float4*)&ws[kk][tx * 4];
            float am[2] = {a2.x, a2.y};
            float bn[4] = {b4.x, b4.y, b4.z, b4.w};
#pragma unroll
            for (int mi = 0; mi < 2; mi++)
#pragma unroll
                for (int ni = 0; ni < 4; ni++)
                    acc[mi][ni] = fmaf(am[mi], bn[ni], acc[mi][ni]);
        }
    }

    float a = prelu_a[0];
#pragma unroll
    for (int mi = 0; mi < 2; mi++) {
        int m = m0 + ty * 2 + mi;
#pragma unroll
        for (int ni = 0; ni < 4; ni++) {
            int n = n0 + tx * 4 + ni;
            float v = acc[mi][ni] + emb_b[n] + emb_W[(size_t)n * INsz + 712] * ts;
            g_x[m * Hsz + n] = (v >= 0.f) ? v : a * v;
        }
    }
}

// ---------------- output projection: out = h @ out_W^T + out_b ----------------
__global__ void out_step_kernel(const float* __restrict__ h,
                                const float* __restrict__ out_W,
                                const float* __restrict__ out_b,
                                float* __restrict__ outp)  // d_out + t*72
{
    __shared__ float hs[8][512];
    __shared__ float ws[64][72];
    const int tid = threadIdx.y * 72 + threadIdx.x;   // 0..575
    const int m0 = blockIdx.x * 8;
    for (int i = tid; i < 8 * 512; i += 576)
        hs[i >> 9][i & 511] = h[(size_t)(m0 + (i >> 9)) * Hsz + (i & 511)];

    float acc = 0.f;
    const int n = threadIdx.x, my = threadIdx.y;
    for (int k0 = 0; k0 < 512; k0 += 64) {
        __syncthreads();
        for (int i = tid; i < 72 * 64; i += 576) {
            int nn = i >> 6, kk = i & 63;
            ws[kk][nn] = out_W[(size_t)nn * Hsz + k0 + kk];
        }
        __syncthreads();
#pragma unroll
        for (int kk = 0; kk < 64; kk++)
            acc = fmaf(hs[my][k0 + kk], ws[kk][n], acc);
    }
    outp[(size_t)(m0 + my) * OUT_ROW + n] = acc + out_b[n];
}

// ---------------- host orchestration ----------------
extern "C" void kernel_launch(void* const* d_in, const int* in_sizes, int n_in,
                              void* d_out, int out_size) {
    const float* label     = (const float*)d_in[1];
    const float* ce        = (const float*)d_in[2];
    const float* traj      = (const float*)d_in[3];
    const float* enc_emb_W = (const float*)d_in[4];
    const float* enc_emb_b = (const float*)d_in[5];
    const float* prelu_a   = (const float*)d_in[6];
    const float* emb_W     = (const float*)d_in[7];
    const float* emb_b     = (const float*)d_in[8];
    const float* out_W     = (const float*)d_in[9];
    const float* out_b     = (const float*)d_in[10];
    const float* enc_Wih   = (const float*)d_in[11];
    const float* enc_Whh   = (const float*)d_in[12];
    const float* enc_bih   = (const float*)d_in[13];
    const float* enc_bhh   = (const float*)d_in[14];
    const float* dec_Wih   = (const float*)d_in[15];
    const float* dec_Whh   = (const float*)d_in[16];
    const float* dec_bih   = (const float*)d_in[17];
    const float* dec_bhh   = (const float*)d_in[18];
    float* out = (float*)d_out;

    // resolve device-global scratch addresses
    float *enc_in_p, *h_base, *c_base, *x_p;
    cudaGetSymbolAddress((void**)&enc_in_p, g_enc_in);
    cudaGetSymbolAddress((void**)&h_base,   g_h);
    cudaGetSymbolAddress((void**)&c_base,   g_c);
    cudaGetSymbolAddress((void**)&x_p,      g_x);
    const size_t HB = (size_t)Bsz * Hsz;
    float* hbuf[2][2] = {{h_base, h_base + HB}, {h_base + 2*HB, h_base + 3*HB}};
    float* cbuf[2]    = {c_base, c_base + HB};

    const int WLH = 4 * Hsz * Hsz;   // per-layer Wih/Whh element count
    const int BLH = 4 * Hsz;         // per-layer bias element count

    // init
    zero_state_kernel<<<(Bsz*Hsz + 255) / 256, 256>>>();
    enc_in_kernel<<<(Bsz*TT*Hsz + 255) / 256, 256>>>(traj, enc_emb_W, enc_emb_b, prelu_a);
    cond_kernel<<<(Bsz*CONDsz + 255) / 256, 256>>>(label, ce);

    dim3 lstm_grid(16, 32);          // 512 CTAs of 128 threads
    dim3 emb_grid(16, 8);
    dim3 out_block(72, 8);

    int cur0 = 0, cur1 = 0;

    // ---- encoder ----
    for (int t = 0; t < TT; t++) {
        lstm_step_kernel<<<lstm_grid, 128>>>(
            enc_in_p + (size_t)t * Hsz, TT * Hsz,
            hbuf[0][cur0],
            enc_Wih, enc_Whh, enc_bih, enc_bhh,
            hbuf[0][cur0 ^ 1], cbuf[0]);
        cur0 ^= 1;
        lstm_step_kernel<<<lstm_grid, 128>>>(
            hbuf[0][cur0], Hsz,
            hbuf[1][cur1],
            enc_Wih + WLH, enc_Whh + WLH, enc_bih + BLH, enc_bhh + BLH,
            hbuf[1][cur1 ^ 1], cbuf[1]);
        cur1 ^= 1;
    }

    // ---- decoder (autoregressive, tf_rate = 0) ----
    for (int t = 0; t < TT; t++) {
        const float* prev = (t == 0) ? nullptr : (out + (size_t)(t - 1) * Fsz);
        float ts = (float)(t + 1) / (float)TT;
        emb_step_kernel<<<emb_grid, 256>>>(prev, emb_W, emb_b, ts, prelu_a);
        lstm_step_kernel<<<lstm_grid, 128>>>(
            x_p, Hsz,
            hbuf[0][cur0],
            dec_Wih, dec_Whh, dec_bih, dec_bhh,
            hbuf[0][cur0 ^ 1], cbuf[0]);
        cur0 ^= 1;
        lstm_step_kernel<<<lstm_grid, 128>>>(
            hbuf[0][cur0], Hsz,
            hbuf[1][cur1],
            dec_Wih + WLH, dec_Whh + WLH, dec_bih + BLH, dec_bhh + BLH,
            hbuf[1][cur1 ^ 1], cbuf[1]);
        cur1 ^= 1;
        out_step_kernel<<<64, out_block>>>(hbuf[1][cur1], out_W, out_b,
                                           out + (size_t)t * Fsz);
    }
}